// round 10
// baseline (speedup 1.0000x reference)
#include <cuda_runtime.h>
#include <cuda_bf16.h>
#include <cstdint>

#define BN   16
#define C    256
#define H    56
#define W    56
#define OC   256
#define HW   (H*W)          // 3136
#define NPIX (BN*HW)        // 50176

#define X_ELEMS  (BN*C*H*W) // 12845056
#define W_ELEMS  (OC*C*3*3) // 589824
#define B_ELEMS  (OC)       // 256

#define NSTAGE 36           // 9 taps x 4 ic-planes (64 ic each)
#define MTILE  128          // output pixels per block
#define NBLK   (NPIX/MTILE) // 392
#define NTHR   256
#define NRING  3

#define RSTRB  144          // padded row stride in bytes (64 bf16 + 16B pad)
#define A_TILE (MTILE*RSTRB)    // 18432 B
#define B_TILE (OC*RSTRB)       // 36864 B
#define BUFSZ  (A_TILE + B_TILE)            // 55296
#define OFF_B0 A_TILE
#define OFF_BIAS (NRING*BUFSZ)              // 165888
#define SMEM_BYTES (OFF_BIAS + OC*4)        // 166912 (1 CTA/SM)

// ---- packed bf16 scratch (device globals; allocation-free rule) ----
__device__ __nv_bfloat16 g_xb[NPIX * C];            // [pix][256 ic]
__device__ __nv_bfloat16 g_wb[NSTAGE * OC * 64];    // [stage][oc][64 ic]

#define XWORK (NPIX * 32)           // 8 channels per work item
#define WWORK (NSTAGE * OC * 64)    // == W_ELEMS

__global__ void pack_fused_kernel(const int* __restrict__ x,
                                  const int* __restrict__ wsrc) {
    int idx = blockIdx.x * blockDim.x + threadIdx.x;
    if (idx < XWORK) {
        int pix = idx % NPIX;
        int grp = idx / NPIX;
        int c0 = grp * 8;
        int w = pix % W;
        int t = pix / W;
        int h = t % H;
        int b = t / H;
        const int* p = x + ((b * C + c0) * H + h) * W + w;
        __align__(16) __nv_bfloat16 v[8];
        #pragma unroll
        for (int k = 0; k < 8; k++) v[k] = __float2bfloat16((float)p[k * HW]);
        *(uint4*)&g_xb[pix * C + c0] = *(const uint4*)v;
    } else if (idx < XWORK + WWORK) {
        int j = idx - XWORK;
        int i  = j & 63;
        int oc = (j >> 6) & 255;
        int s  = j >> 14;            // 0..35
        int tap = s >> 2, plane = s & 3;
        int ic = plane * 64 + i;
        g_wb[j] = __float2bfloat16((float)wsrc[(oc * C + ic) * 9 + tap]);
    }
}

__device__ __forceinline__ uint32_t smem_u32(const void* p) {
    uint32_t a;
    asm("{ .reg .u64 t; cvta.to.shared.u64 t, %1; cvt.u32.u64 %0, t; }" : "=r"(a) : "l"(p));
    return a;
}

__device__ __forceinline__ void mma_bf16(float* c, const unsigned* a, const unsigned* b) {
    asm volatile(
        "mma.sync.aligned.m16n8k16.row.col.f32.bf16.bf16.f32 "
        "{%0,%1,%2,%3}, {%4,%5,%6,%7}, {%8,%9}, {%0,%1,%2,%3};"
        : "+f"(c[0]), "+f"(c[1]), "+f"(c[2]), "+f"(c[3])
        : "r"(a[0]), "r"(a[1]), "r"(a[2]), "r"(a[3]), "r"(b[0]), "r"(b[1]));
}

#define LDSM_X4(r0, r1, r2, r3, addr)                                        \
    asm volatile("ldmatrix.sync.aligned.m8n8.x4.shared.b16 {%0,%1,%2,%3}, [%4];" \
        : "=r"(r0), "=r"(r1), "=r"(r2), "=r"(r3) : "r"(addr))

#define CP16(dst, src, sz) \
    asm volatile("cp.async.cg.shared.global [%0], [%1], 16, %2;" \
                 :: "r"(dst), "l"(src), "r"(sz))
#define CP_COMMIT() asm volatile("cp.async.commit_group;" ::: "memory")
#define CP_WAIT1()  asm volatile("cp.async.wait_group 1;" ::: "memory")

__global__ __launch_bounds__(NTHR, 1)
void conv_hmma_kernel(const int* __restrict__ bias, float* __restrict__ out) {
    extern __shared__ __align__(16) char dsm[];
    const uint32_t sbase = smem_u32(dsm);
    float* sbias = (float*)(dsm + OFF_BIAS);

    const int tid = threadIdx.x;
    const int lane = tid & 31;
    const int wid  = tid >> 5;       // 0..7
    const int g    = lane >> 2;      // groupID 0..7
    const int tig  = lane & 3;       // thread-in-group 0..3
    const int wm   = wid & 1;        // 2 M tiles of 64 px
    const int wn   = wid >> 1;       // 4 N tiles of 64 oc
    const int p0   = blockIdx.x * MTILE;

    sbias[tid] = (float)bias[tid];

    // ---- hoisted per-thread copy state (stage-invariant) ----
    int hA[4], wA[4];
    const __nv_bfloat16* srcA[4];
    uint32_t dstA[4];
    #pragma unroll
    for (int it = 0; it < 4; it++) {
        int chunk = tid + it * NTHR;         // 0..1023
        int m = chunk >> 3, j = chunk & 7;
        int p = p0 + m;
        int b = p / HW, rem = p - b * HW;
        hA[it] = rem / W;
        wA[it] = rem - hA[it] * W;
        srcA[it] = g_xb + (size_t)b * HW * C + j * 8;
        dstA[it] = sbase + (uint32_t)(m * RSTRB + j * 16);
    }
    uint32_t dstB[8];
    #pragma unroll
    for (int it = 0; it < 8; it++) {
        int chunk = tid + it * NTHR;         // 0..2047
        int ocl = chunk >> 3, j = chunk & 7;
        dstB[it] = sbase + (uint32_t)(OFF_B0 + ocl * RSTRB + j * 16);
    }

    // ldmatrix per-thread offsets (within a buffer)
    const uint32_t aoff = (uint32_t)((wm * 64 + (lane & 15)) * RSTRB + ((lane >> 4) & 1) * 16);
    const uint32_t boff = (uint32_t)(OFF_B0 + ((wn * 64) + ((lane >> 4) & 1) * 8 + (lane & 7)) * RSTRB
                                     + ((lane >> 3) & 1) * 16);

    float acc[4][8][4];
    #pragma unroll
    for (int i = 0; i < 4; i++)
        #pragma unroll
        for (int j = 0; j < 8; j++)
            #pragma unroll
            for (int r = 0; r < 4; r++) acc[i][j][r] = 0.0f;

    auto stage_copy = [&](int s, int buf) {
        const int tap = s >> 2, plane = s & 3;
        const int dh = tap / 3 - 1, dw = tap % 3 - 1;
        const uint32_t bo = (uint32_t)(buf * BUFSZ);
        #pragma unroll
        for (int it = 0; it < 4; it++) {
            int h2 = hA[it] + dh, w2 = wA[it] + dw;
            bool ok = ((unsigned)h2 < (unsigned)H) && ((unsigned)w2 < (unsigned)W);
            int off = ok ? ((h2 * W + w2) * C + plane * 64) : 0;
            int sz = ok ? 16 : 0;
            CP16(dstA[it] + bo, srcA[it] + off, sz);
        }
        const __nv_bfloat16* ws = g_wb + (size_t)s * (OC * 64);
        #pragma unroll
        for (int it = 0; it < 8; it++) {
            int chunk = tid + it * NTHR;
            CP16(dstB[it] + bo, ws + chunk * 8, 16);
        }
    };

    // prologue: stages 0..1
    #pragma unroll
    for (int ps = 0; ps < NRING - 1; ps++) {
        stage_copy(ps, ps);
        CP_COMMIT();
    }

    int buf = 0;
    for (int s = 0; s < NSTAGE; s++) {
        CP_WAIT1();
        __syncthreads();
        const int sp = s + NRING - 1;
        int pbuf = buf + 2; if (pbuf >= NRING) pbuf -= NRING;
        if (sp < NSTAGE) stage_copy(sp, pbuf);
        CP_COMMIT();

        const uint32_t bufo = (uint32_t)(buf * BUFSZ);
        const uint32_t aT = sbase + bufo + aoff;
        const uint32_t bT = sbase + bufo + boff;

        // ---- register-double-buffered fragment pipeline across kq ----
        unsigned a[2][4][4];
        unsigned bf[2][8][2];
        // load kq = 0
        #pragma unroll
        for (int i = 0; i < 4; i++)
            LDSM_X4(a[0][i][0], a[0][i][1], a[0][i][2], a[0][i][3],
                    aT + (uint32_t)(i * 16 * RSTRB));
        #pragma unroll
        for (int jp = 0; jp < 4; jp++)
            LDSM_X4(bf[0][2*jp][0], bf[0][2*jp][1], bf[0][2*jp+1][0], bf[0][2*jp+1][1],
                    bT + (uint32_t)(jp * 16 * RSTRB));

        #pragma unroll
        for (int kq = 0; kq < 4; kq++) {
            const int cur = kq & 1, nxt = cur ^ 1;
            if (kq < 3) {
                const uint32_t kb = (uint32_t)((kq + 1) * 32);
                #pragma unroll
                for (int i = 0; i < 4; i++)
                    LDSM_X4(a[nxt][i][0], a[nxt][i][1], a[nxt][i][2], a[nxt][i][3],
                            aT + kb + (uint32_t)(i * 16 * RSTRB));
                #pragma unroll
                for (int jp = 0; jp < 4; jp++)
                    LDSM_X4(bf[nxt][2*jp][0], bf[nxt][2*jp][1],
                            bf[nxt][2*jp+1][0], bf[nxt][2*jp+1][1],
                            bT + kb + (uint32_t)(jp * 16 * RSTRB));
            }
            #pragma unroll
            for (int i = 0; i < 4; i++)
                #pragma unroll
                for (int j = 0; j < 8; j++)
                    mma_bf16(acc[i][j], a[cur][i], bf[cur][j]);
        }
        if (++buf == NRING) buf = 0;
    }

    // epilogue: +bias, float32 out (NCHW)
    #pragma unroll
    for (int i = 0; i < 4; i++) {
        int r = wm * 64 + i * 16 + g;
        int px0 = p0 + r, px1 = px0 + 8;
        int b0 = px0 / HW, rem0 = px0 - b0 * HW;
        int b1 = px1 / HW, rem1 = px1 - b1 * HW;
        float* base0 = out + (size_t)b0 * (OC * HW) + rem0;
        float* base1 = out + (size_t)b1 * (OC * HW) + rem1;
        #pragma unroll
        for (int j = 0; j < 8; j++) {
            int oc = wn * 64 + j * 8 + tig * 2;
            float bv0 = sbias[oc], bv1 = sbias[oc + 1];
            base0[(size_t)oc * HW]       = acc[i][j][0] + bv0;
            base0[(size_t)(oc + 1) * HW] = acc[i][j][1] + bv1;
            base1[(size_t)oc * HW]       = acc[i][j][2] + bv0;
            base1[(size_t)(oc + 1) * HW] = acc[i][j][3] + bv1;
        }
    }
}

extern "C" void kernel_launch(void* const* d_in, const int* in_sizes, int n_in,
                              void* d_out, int out_size) {
    const int* x    = nullptr;
    const int* wsrc = nullptr;
    const int* bias = nullptr;
    for (int i = 0; i < n_in; i++) {
        if (in_sizes[i] == X_ELEMS)      x    = (const int*)d_in[i];
        else if (in_sizes[i] == W_ELEMS) wsrc = (const int*)d_in[i];
        else if (in_sizes[i] == B_ELEMS) bias = (const int*)d_in[i];
    }
    if (!x)    x    = (const int*)d_in[0];
    if (!wsrc) wsrc = (const int*)d_in[1];
    if (!bias) bias = (const int*)d_in[2];

    float* out = (float*)d_out;

    pack_fused_kernel<<<(XWORK + WWORK + 255) / 256, 256>>>(x, wsrc);

    cudaFuncSetAttribute(conv_hmma_kernel,
                         cudaFuncAttributeMaxDynamicSharedMemorySize, SMEM_BYTES);
    conv_hmma_kernel<<<NBLK, NTHR, SMEM_BYTES>>>(bias, out);
}

// round 11
// speedup vs baseline: 1.0792x; 1.0792x over previous
#include <cuda_runtime.h>
#include <cuda_bf16.h>
#include <cstdint>

#define BN   16
#define C    256
#define H    56
#define W    56
#define OC   256
#define HW   (H*W)          // 3136
#define NPIX (BN*HW)        // 50176

#define X_ELEMS  (BN*C*H*W) // 12845056
#define W_ELEMS  (OC*C*3*3) // 589824
#define B_ELEMS  (OC)       // 256

#define NSTAGE 36           // 9 taps x 4 ic-planes (64 ic each)
#define MTILE  128          // output pixels per block
#define NBLK   (NPIX/MTILE) // 392
#define NTHR   512
#define NRING  4

#define RSTRB  144          // padded row stride in bytes (64 bf16 + 16B pad)
#define A_TILE (MTILE*RSTRB)    // 18432 B
#define B_TILE (OC*RSTRB)       // 36864 B
#define BUFSZ  (A_TILE + B_TILE)            // 55296
#define OFF_B0 A_TILE
#define OFF_BIAS (NRING*BUFSZ)              // 221184
#define SMEM_BYTES (OFF_BIAS + OC*4)        // 222208

// ---- packed bf16 scratch (device globals; allocation-free rule) ----
__device__ __nv_bfloat16 g_xb[NPIX * C];            // [pix][256 ic]
__device__ __nv_bfloat16 g_wb[NSTAGE * OC * 64];    // [stage][oc][64 ic]

#define XWORK (NPIX * 32)           // 8 channels per work item
#define WWORK (NSTAGE * OC * 64)    // == W_ELEMS

__global__ void pack_fused_kernel(const int* __restrict__ x,
                                  const int* __restrict__ wsrc) {
    int idx = blockIdx.x * blockDim.x + threadIdx.x;
    if (idx < XWORK) {
        int pix = idx % NPIX;
        int grp = idx / NPIX;
        int c0 = grp * 8;
        int w = pix % W;
        int t = pix / W;
        int h = t % H;
        int b = t / H;
        const int* p = x + ((b * C + c0) * H + h) * W + w;
        __align__(16) __nv_bfloat16 v[8];
        #pragma unroll
        for (int k = 0; k < 8; k++) v[k] = __float2bfloat16((float)p[k * HW]);
        *(uint4*)&g_xb[pix * C + c0] = *(const uint4*)v;
    } else if (idx < XWORK + WWORK) {
        int j = idx - XWORK;
        int i  = j & 63;
        int oc = (j >> 6) & 255;
        int s  = j >> 14;            // 0..35
        int tap = s >> 2, plane = s & 3;
        int ic = plane * 64 + i;
        g_wb[j] = __float2bfloat16((float)wsrc[(oc * C + ic) * 9 + tap]);
    }
}

__device__ __forceinline__ uint32_t smem_u32(const void* p) {
    uint32_t a;
    asm("{ .reg .u64 t; cvta.to.shared.u64 t, %1; cvt.u32.u64 %0, t; }" : "=r"(a) : "l"(p));
    return a;
}

__device__ __forceinline__ void mma_bf16(float* c, const unsigned* a, const unsigned* b) {
    asm volatile(
        "mma.sync.aligned.m16n8k16.row.col.f32.bf16.bf16.f32 "
        "{%0,%1,%2,%3}, {%4,%5,%6,%7}, {%8,%9}, {%0,%1,%2,%3};"
        : "+f"(c[0]), "+f"(c[1]), "+f"(c[2]), "+f"(c[3])
        : "r"(a[0]), "r"(a[1]), "r"(a[2]), "r"(a[3]), "r"(b[0]), "r"(b[1]));
}

#define LDSM_X4(r0, r1, r2, r3, addr)                                        \
    asm volatile("ldmatrix.sync.aligned.m8n8.x4.shared.b16 {%0,%1,%2,%3}, [%4];" \
        : "=r"(r0), "=r"(r1), "=r"(r2), "=r"(r3) : "r"(addr))

#define CP16(dst, src, sz) \
    asm volatile("cp.async.cg.shared.global [%0], [%1], 16, %2;" \
                 :: "r"(dst), "l"(src), "r"(sz))
#define CP_COMMIT() asm volatile("cp.async.commit_group;" ::: "memory")
#define CP_WAIT2()  asm volatile("cp.async.wait_group 2;" ::: "memory")

__global__ __launch_bounds__(NTHR, 1)
void conv_hmma_kernel(const int* __restrict__ bias, float* __restrict__ out) {
    extern __shared__ __align__(16) char dsm[];
    const uint32_t sbase = smem_u32(dsm);
    float* sbias = (float*)(dsm + OFF_BIAS);

    const int tid = threadIdx.x;
    const int lane = tid & 31;
    const int wid  = tid >> 5;       // 0..15
    const int g    = lane >> 2;      // groupID 0..7
    const int tig  = lane & 3;       // thread-in-group 0..3
    const int wm   = wid & 3;        // 4 M tiles of 32 px
    const int wn   = wid >> 2;       // 4 N tiles of 64 oc
    const int p0   = blockIdx.x * MTILE;

    if (tid < OC) sbias[tid] = (float)bias[tid];

    // ---- hoisted per-thread copy state (stage-invariant) ----
    int hA[2], wA[2];
    const __nv_bfloat16* srcA[2];
    uint32_t dstA[2];
    #pragma unroll
    for (int it = 0; it < 2; it++) {
        int chunk = tid + it * NTHR;         // 0..1023
        int m = chunk >> 3, j = chunk & 7;
        int p = p0 + m;
        int b = p / HW, rem = p - b * HW;
        hA[it] = rem / W;
        wA[it] = rem - hA[it] * W;
        srcA[it] = g_xb + (size_t)b * HW * C + j * 8;
        dstA[it] = sbase + (uint32_t)(m * RSTRB + j * 16);
    }
    uint32_t dstB[4];
    #pragma unroll
    for (int it = 0; it < 4; it++) {
        int chunk = tid + it * NTHR;         // 0..2047
        int oc = chunk >> 3, j = chunk & 7;
        dstB[it] = sbase + (uint32_t)(OFF_B0 + oc * RSTRB + j * 16);
    }

    // ldmatrix per-thread offsets (within a buffer)
    const uint32_t aoff = (uint32_t)((wm * 32 + (lane & 15)) * RSTRB + ((lane >> 4) & 1) * 16);
    const uint32_t boff = (uint32_t)(OFF_B0 + ((wn * 64) + ((lane >> 4) & 1) * 8 + (lane & 7)) * RSTRB
                                     + ((lane >> 3) & 1) * 16);

    // per-warp k-quarter rotation: de-phases crossbar vs tensor across warps
    const uint32_t krot = (uint32_t)(wid & 3);

    float acc[2][8][4];
    #pragma unroll
    for (int i = 0; i < 2; i++)
        #pragma unroll
        for (int j = 0; j < 8; j++)
            #pragma unroll
            for (int r = 0; r < 4; r++) acc[i][j][r] = 0.0f;

    auto stage_copy = [&](int s, int buf) {
        const int tap = s >> 2, plane = s & 3;
        const int dh = tap / 3 - 1, dw = tap % 3 - 1;
        const uint32_t bo = (uint32_t)(buf * BUFSZ);
        #pragma unroll
        for (int it = 0; it < 2; it++) {
            int h2 = hA[it] + dh, w2 = wA[it] + dw;
            bool ok = ((unsigned)h2 < (unsigned)H) && ((unsigned)w2 < (unsigned)W);
            int off = ok ? ((h2 * W + w2) * C + plane * 64) : 0;
            int sz = ok ? 16 : 0;
            CP16(dstA[it] + bo, srcA[it] + off, sz);
        }
        const __nv_bfloat16* ws = g_wb + (size_t)s * (OC * 64);
        #pragma unroll
        for (int it = 0; it < 4; it++) {
            int chunk = tid + it * NTHR;
            CP16(dstB[it] + bo, ws + chunk * 8, 16);
        }
    };

    // prologue: stages 0..2
    #pragma unroll
    for (int ps = 0; ps < NRING - 1; ps++) {
        stage_copy(ps, ps);
        CP_COMMIT();
    }

    for (int s = 0; s < NSTAGE; s++) {
        CP_WAIT2();
        __syncthreads();
        const int sp = s + NRING - 1;
        if (sp < NSTAGE) stage_copy(sp, sp & (NRING - 1));
        CP_COMMIT();

        const uint32_t bufo = (uint32_t)((s & (NRING - 1)) * BUFSZ);
        const uint32_t aT = sbase + bufo + aoff;
        const uint32_t bT = sbase + bufo + boff;
        #pragma unroll
        for (int kqi = 0; kqi < 4; kqi++) {
            const uint32_t kb = (((uint32_t)kqi + krot) & 3u) * 32u;
            unsigned a[2][4];
            #pragma unroll
            for (int i = 0; i < 2; i++)
                LDSM_X4(a[i][0], a[i][1], a[i][2], a[i][3],
                        aT + kb + (uint32_t)(i * 16 * RSTRB));
            unsigned bf[8][2];
            #pragma unroll
            for (int jp = 0; jp < 4; jp++)
                LDSM_X4(bf[2*jp][0], bf[2*jp][1], bf[2*jp+1][0], bf[2*jp+1][1],
                        bT + kb + (uint32_t)(jp * 16 * RSTRB));
            #pragma unroll
            for (int i = 0; i < 2; i++)
                #pragma unroll
                for (int j = 0; j < 8; j++)
                    mma_bf16(acc[i][j], a[i], bf[j]);
        }
    }

    // epilogue: +bias, float32 out (NCHW)
    #pragma unroll
    for (int i = 0; i < 2; i++) {
        int r = wm * 32 + i * 16 + g;
        int px0 = p0 + r, px1 = px0 + 8;
        int b0 = px0 / HW, rem0 = px0 - b0 * HW;
        int b1 = px1 / HW, rem1 = px1 - b1 * HW;
        float* base0 = out + (size_t)b0 * (OC * HW) + rem0;
        float* base1 = out + (size_t)b1 * (OC * HW) + rem1;
        #pragma unroll
        for (int j = 0; j < 8; j++) {
            int oc = wn * 64 + j * 8 + tig * 2;
            float bv0 = sbias[oc], bv1 = sbias[oc + 1];
            base0[(size_t)oc * HW]       = acc[i][j][0] + bv0;
            base0[(size_t)(oc + 1) * HW] = acc[i][j][1] + bv1;
            base1[(size_t)oc * HW]       = acc[i][j][2] + bv0;
            base1[(size_t)(oc + 1) * HW] = acc[i][j][3] + bv1;
        }
    }
}

extern "C" void kernel_launch(void* const* d_in, const int* in_sizes, int n_in,
                              void* d_out, int out_size) {
    const int* x    = nullptr;
    const int* wsrc = nullptr;
    const int* bias = nullptr;
    for (int i = 0; i < n_in; i++) {
        if (in_sizes[i] == X_ELEMS)      x    = (const int*)d_in[i];
        else if (in_sizes[i] == W_ELEMS) wsrc = (const int*)d_in[i];
        else if (in_sizes[i] == B_ELEMS) bias = (const int*)d_in[i];
    }
    if (!x)    x    = (const int*)d_in[0];
    if (!wsrc) wsrc = (const int*)d_in[1];
    if (!bias) bias = (const int*)d_in[2];

    float* out = (float*)d_out;

    pack_fused_kernel<<<(XWORK + WWORK + 255) / 256, 256>>>(x, wsrc);

    cudaFuncSetAttribute(conv_hmma_kernel,
                         cudaFuncAttributeMaxDynamicSharedMemorySize, SMEM_BYTES);
    conv_hmma_kernel<<<NBLK, NTHR, SMEM_BYTES>>>(bias, out);
}